// round 1
// baseline (speedup 1.0000x reference)
#include <cuda_runtime.h>

// ---------------- problem constants ----------------
#define B_    2
#define C_    64
#define H_    512
#define W_    512
#define T_    16
#define GH_   32
#define GW_   32
#define K_    1024          // tiles per sample
#define KMAX_ 256
#define HID_  128
#define HW_   (H_*W_)       // 262144
#define CHW_  (C_*HW_)      // 16777216

// output layout (flatten-concat of the tuple, all f32)
#define HEAVY_OFF  0
#define DET_OFF    33554432
#define ALPHA_OFF  67108864
#define P_OFF      67633152
#define G_OFF      67635200
#define COST_OFF   67637248
#define BL_OFF     67637249

__device__ int g_sel[B_*K_];

// ---------------- math helpers ----------------
__device__ __forceinline__ float fast_sigmoid(float v) {
    return __fdividef(1.f, 1.f + __expf(-v));
}
// jax.nn.gelu default approximate=True (tanh form)
__device__ __forceinline__ float gelu_tanh(float v) {
    float z  = 0.7978845608028654f * fmaf(0.044715f * v, v * v, v);
    float e  = __expf(2.f * z);
    float th = 1.f - __fdividef(2.f, e + 1.f);   // tanh(z)
    return 0.5f * v * (1.f + th);
}

// ---------------- gate / stats kernel (1 block, 1024 thr) ----------------
__global__ void gate_kernel(const float* __restrict__ u, float* __restrict__ out) {
    __shared__ float red[1024];
    int t = threadIdx.x;
    float partial = 0.f;
    #pragma unroll
    for (int e = t; e < B_*K_; e += 1024) {
        float uv = u[e];
        float p  = fast_sigmoid(uv);
        float hard = (uv >= 0.f) ? 1.f : 0.f;
        float gate = (hard + p) - p;   // STE value, same fp op order as ref
        out[P_OFF + e] = p;
        out[G_OFF + e] = gate;
        partial += fmaf(p, 0.9f, 0.1f);   // p*1.0 + (1-p)*0.1
    }
    red[t] = partial;
    __syncthreads();
    for (int s = 512; s > 0; s >>= 1) {
        if (t < s) red[t] += red[t + s];
        __syncthreads();
    }
    if (t == 0) {
        float cost = red[0];
        out[COST_OFF] = cost;
        float bl = cost - 1024.f;      // BUDGET_TOTAL*B = 512*2
        out[BL_OFF] = bl > 0.f ? bl : 0.f;
    }
}

// ---------------- selection kernel (rank-count top-KMAX) ----------------
// grid = 32 blocks (16 per sample), 256 threads. 4 threads per element.
__global__ void select_kernel(const float* __restrict__ u) {
    __shared__ float us[K_];
    int b   = blockIdx.x >> 4;
    int seg = blockIdx.x & 15;
    int t   = threadIdx.x;
    for (int i = t; i < K_; i += 256) us[i] = u[b*K_ + i];
    __syncthreads();
    int e   = seg*64 + (t >> 2);
    int sub = t & 3;
    float ue = us[e];
    int cnt = 0;
    if (ue >= 0.f) {
        int j0 = sub * 256;
        #pragma unroll 4
        for (int j = j0; j < j0 + 256; ++j) {
            float uj = us[j];
            // masked value of gated-off elems is -1e30: never outranks ue>=0
            if (uj >= 0.f && (uj > ue || (uj == ue && j < e))) cnt++;
        }
    }
    cnt += __shfl_xor_sync(0xFFFFFFFFu, cnt, 1);
    cnt += __shfl_xor_sync(0xFFFFFFFFu, cnt, 2);
    if (sub == 0) g_sel[b*K_ + e] = (ue >= 0.f && cnt < KMAX_) ? 1 : 0;
}

// ---------------- main tile kernel ----------------
// grid = B*K blocks, 256 threads (one per pixel of the 16x16 tile).
// Selected tile: per-pixel 64->128->64 MLP, weights in shared with W1
// transposed so weight fetches are broadcast LDS.128 (4 FMA per LDS instr).
// Unselected tile: float4 copy heavy=x, zero detail/alpha.
#define SM_W1T 0          // [128][64] transposed W1
#define SM_W2  8192       // [128][64]
#define SM_B1  16384
#define SM_B2  16512
#define SM_WA  16576
#define SM_BA  16640
#define SMEM_FLOATS 16641
#define SMEM_BYTES (SMEM_FLOATS*4)

__global__ void __launch_bounds__(256)
main_kernel(const float* __restrict__ x,
            const float* __restrict__ W1, const float* __restrict__ b1,
            const float* __restrict__ W2, const float* __restrict__ b2,
            const float* __restrict__ Wa, const float* __restrict__ ba,
            float* __restrict__ out) {
    extern __shared__ float sm[];
    int blk = blockIdx.x;
    int b   = blk >> 10;
    int k   = blk & (K_-1);
    int gh  = k >> 5, gw = k & 31;
    int t   = threadIdx.x;

    int tile_base = b*CHW_ + (gh*T_)*W_ + gw*T_;   // < 2^26, int ok
    float* heavy = out + HEAVY_OFF;
    float* det   = out + DET_OFF;
    float* alp   = out + ALPHA_OFF;

    if (!g_sel[blk]) {
        // ---- cheap path: heavy = x, detail_out = 0, alpha_out = 0 ----
        #pragma unroll 4
        for (int i = t; i < C_*T_*4; i += 256) {   // 4096 float4s
            int c = i >> 6; int rem = i & 63;
            int r = rem >> 2; int q = rem & 3;
            int off = tile_base + c*HW_ + r*W_ + q*4;
            float4 v = *(const float4*)(x + off);
            *(float4*)(heavy + off) = v;
            *(float4*)(det   + off) = make_float4(0.f,0.f,0.f,0.f);
        }
        if (t < 64) {
            int r = t >> 2, q = t & 3;
            int aoff = b*HW_ + (gh*T_ + r)*W_ + gw*T_ + q*4;
            *(float4*)(alp + aoff) = make_float4(0.f,0.f,0.f,0.f);
        }
        return;
    }

    // ---- load weights to shared (W1 transposed for contiguous d-rows) ----
    for (int i = t; i < C_*HID_; i += 256) {
        int d = i >> 6, c = i & 63;
        sm[SM_W1T + i] = W1[c*HID_ + d];
        sm[SM_W2  + i] = W2[i];
    }
    if (t < HID_) sm[SM_B1 + t] = b1[t];
    if (t < C_)  { sm[SM_B2 + t] = b2[t]; sm[SM_WA + t] = Wa[t]; }
    if (t == 0)   sm[SM_BA] = ba[0];
    __syncthreads();

    int r = t >> 4, cpos = t & 15;
    int pbase = tile_base + r*W_ + cpos;

    float xr[C_];
    #pragma unroll
    for (int c = 0; c < C_; ++c) xr[c] = x[pbase + c*HW_];

    // alpha = sigmoid(x . Wa + ba)
    float ad = sm[SM_BA];
    #pragma unroll
    for (int c = 0; c < C_; ++c) ad = fmaf(xr[c], sm[SM_WA + c], ad);
    float alpha = fast_sigmoid(ad);

    float acc[C_];
    #pragma unroll
    for (int c = 0; c < C_; ++c) acc[c] = sm[SM_B2 + c];

    #pragma unroll 2
    for (int d = 0; d < HID_; ++d) {
        const float4* w1r = (const float4*)(sm + SM_W1T + d*C_);
        float s0 = 0.f, s1 = 0.f, s2 = 0.f, s3 = 0.f;
        #pragma unroll
        for (int c4 = 0; c4 < 16; ++c4) {
            float4 wv = w1r[c4];
            s0 = fmaf(xr[c4*4+0], wv.x, s0);
            s1 = fmaf(xr[c4*4+1], wv.y, s1);
            s2 = fmaf(xr[c4*4+2], wv.z, s2);
            s3 = fmaf(xr[c4*4+3], wv.w, s3);
        }
        float hv = gelu_tanh(((s0 + s1) + (s2 + s3)) + sm[SM_B1 + d]);
        const float4* w2r = (const float4*)(sm + SM_W2 + d*C_);
        #pragma unroll
        for (int c4 = 0; c4 < 16; ++c4) {
            float4 wv = w2r[c4];
            acc[c4*4+0] = fmaf(hv, wv.x, acc[c4*4+0]);
            acc[c4*4+1] = fmaf(hv, wv.y, acc[c4*4+1]);
            acc[c4*4+2] = fmaf(hv, wv.z, acc[c4*4+2]);
            acc[c4*4+3] = fmaf(hv, wv.w, acc[c4*4+3]);
        }
    }

    int aoff = b*HW_ + (gh*T_ + r)*W_ + gw*T_ + cpos;
    alp[aoff] = alpha;
    #pragma unroll
    for (int c = 0; c < C_; ++c) {
        int off = pbase + c*HW_;
        det[off]   = acc[c];                      // detail_out (mask=1)
        heavy[off] = fmaf(alpha, acc[c], xr[c]);  // x + alpha*detail
    }
}

// ---------------- launcher ----------------
extern "C" void kernel_launch(void* const* d_in, const int* in_sizes, int n_in,
                              void* d_out, int out_size) {
    const float* x  = (const float*)d_in[0];
    const float* u  = (const float*)d_in[1];
    const float* W1 = (const float*)d_in[2];
    const float* b1 = (const float*)d_in[3];
    const float* W2 = (const float*)d_in[4];
    const float* b2 = (const float*)d_in[5];
    const float* Wa = (const float*)d_in[6];
    const float* ba = (const float*)d_in[7];
    float* out = (float*)d_out;

    cudaFuncSetAttribute(main_kernel,
                         cudaFuncAttributeMaxDynamicSharedMemorySize, SMEM_BYTES);

    gate_kernel<<<1, 1024>>>(u, out);
    select_kernel<<<32, 256>>>(u);
    main_kernel<<<B_*K_, 256, SMEM_BYTES>>>(x, W1, b1, W2, b2, Wa, ba, out);
}

// round 2
// speedup vs baseline: 1.0618x; 1.0618x over previous
#include <cuda_runtime.h>

// ---------------- problem constants ----------------
#define B_    2
#define C_    64
#define H_    512
#define W_    512
#define T_    16
#define GH_   32
#define GW_   32
#define K_    1024          // tiles per sample
#define KMAX_ 256
#define HID_  128
#define HW_   (H_*W_)       // 262144
#define CHW_  (C_*HW_)      // 16777216

// output layout (flatten-concat of the tuple, all f32)
#define HEAVY_OFF  0
#define DET_OFF    33554432
#define ALPHA_OFF  67108864
#define P_OFF      67633152
#define G_OFF      67635200
#define COST_OFF   67637248
#define BL_OFF     67637249

__device__ int g_sel[B_*K_];

typedef unsigned long long u64;

// ---------------- packed f32x2 helpers (Blackwell FFMA2 path) ----------------
__device__ __forceinline__ u64 pack2(float lo, float hi) {
    u64 r; asm("mov.b64 %0, {%1, %2};" : "=l"(r) : "f"(lo), "f"(hi)); return r;
}
__device__ __forceinline__ void unpack2(u64 v, float& lo, float& hi) {
    asm("mov.b64 {%0, %1}, %2;" : "=f"(lo), "=f"(hi) : "l"(v));
}
__device__ __forceinline__ u64 ffma2(u64 a, u64 b, u64 c) {
    u64 d; asm("fma.rn.f32x2 %0, %1, %2, %3;" : "=l"(d) : "l"(a), "l"(b), "l"(c));
    return d;
}

// ---------------- math helpers ----------------
__device__ __forceinline__ float fast_sigmoid(float v) {
    return __fdividef(1.f, 1.f + __expf(-v));
}
// jax.nn.gelu tanh form, MUFU.TANH (1 MUFU, short chain)
__device__ __forceinline__ float gelu_tanh(float v) {
    float z  = 0.7978845608028654f * fmaf(0.044715f * v, v * v, v);
    float th; asm("tanh.approx.f32 %0, %1;" : "=f"(th) : "f"(z));
    return 0.5f * v * (1.f + th);
}

// ---------------- gate / stats kernel (1 block, 1024 thr) ----------------
__global__ void gate_kernel(const float* __restrict__ u, float* __restrict__ out) {
    __shared__ float red[1024];
    int t = threadIdx.x;
    float partial = 0.f;
    #pragma unroll
    for (int e = t; e < B_*K_; e += 1024) {
        float uv = u[e];
        float p  = fast_sigmoid(uv);
        float hard = (uv >= 0.f) ? 1.f : 0.f;
        float gate = (hard + p) - p;   // STE value
        out[P_OFF + e] = p;
        out[G_OFF + e] = gate;
        partial += fmaf(p, 0.9f, 0.1f);   // p*1.0 + (1-p)*0.1
    }
    red[t] = partial;
    __syncthreads();
    for (int s = 512; s > 0; s >>= 1) {
        if (t < s) red[t] += red[t + s];
        __syncthreads();
    }
    if (t == 0) {
        float cost = red[0];
        out[COST_OFF] = cost;
        float bl = cost - 1024.f;      // BUDGET_TOTAL*B = 512*2
        out[BL_OFF] = bl > 0.f ? bl : 0.f;
    }
}

// ---------------- selection kernel (rank-count top-KMAX) ----------------
__global__ void select_kernel(const float* __restrict__ u) {
    __shared__ float us[K_];
    int b   = blockIdx.x >> 4;
    int seg = blockIdx.x & 15;
    int t   = threadIdx.x;
    for (int i = t; i < K_; i += 256) us[i] = u[b*K_ + i];
    __syncthreads();
    int e   = seg*64 + (t >> 2);
    int sub = t & 3;
    float ue = us[e];
    int cnt = 0;
    if (ue >= 0.f) {
        int j0 = sub * 256;
        #pragma unroll 4
        for (int j = j0; j < j0 + 256; ++j) {
            float uj = us[j];
            if (uj >= 0.f && (uj > ue || (uj == ue && j < e))) cnt++;
        }
    }
    cnt += __shfl_xor_sync(0xFFFFFFFFu, cnt, 1);
    cnt += __shfl_xor_sync(0xFFFFFFFFu, cnt, 2);
    if (sub == 0) g_sel[b*K_ + e] = (ue >= 0.f && cnt < KMAX_) ? 1 : 0;
}

// ---------------- main tile kernel ----------------
// grid = B*K blocks, 256 threads (one per pixel of the 16x16 tile).
// Selected tile: per-pixel 64->128->64 MLP in packed f32x2, weights broadcast
// from shared via 16B loads. d-loop unrolled x2 to overlap the two gelu chains.
#define SM_W1T 0          // [128][64] transposed W1 (row d contiguous over c)
#define SM_W2  8192       // [128][64]
#define SM_B1  16384
#define SM_B2  16512
#define SM_WA  16576
#define SM_BA  16640
#define SMEM_FLOATS 16644
#define SMEM_BYTES (SMEM_FLOATS*4)

__global__ void __launch_bounds__(256)
main_kernel(const float* __restrict__ x,
            const float* __restrict__ W1, const float* __restrict__ b1,
            const float* __restrict__ W2, const float* __restrict__ b2,
            const float* __restrict__ Wa, const float* __restrict__ ba,
            float* __restrict__ out) {
    extern __shared__ float sm[];
    int blk = blockIdx.x;
    int b   = blk >> 10;
    int k   = blk & (K_-1);
    int gh  = k >> 5, gw = k & 31;
    int t   = threadIdx.x;

    int tile_base = b*CHW_ + (gh*T_)*W_ + gw*T_;
    float* heavy = out + HEAVY_OFF;
    float* det   = out + DET_OFF;
    float* alp   = out + ALPHA_OFF;

    if (!g_sel[blk]) {
        // ---- cheap path: heavy = x, detail_out = 0, alpha_out = 0 ----
        #pragma unroll 4
        for (int i = t; i < C_*T_*4; i += 256) {   // 4096 float4s
            int c = i >> 6; int rem = i & 63;
            int r = rem >> 2; int q = rem & 3;
            int off = tile_base + c*HW_ + r*W_ + q*4;
            float4 v = *(const float4*)(x + off);
            *(float4*)(heavy + off) = v;
            *(float4*)(det   + off) = make_float4(0.f,0.f,0.f,0.f);
        }
        if (t < 64) {
            int r = t >> 2, q = t & 3;
            int aoff = b*HW_ + (gh*T_ + r)*W_ + gw*T_ + q*4;
            *(float4*)(alp + aoff) = make_float4(0.f,0.f,0.f,0.f);
        }
        return;
    }

    // ---- load weights to shared (W1 transposed so row d is contiguous) ----
    for (int i = t; i < C_*HID_; i += 256) {
        int d = i >> 6, c = i & 63;
        sm[SM_W1T + i] = W1[c*HID_ + d];
        sm[SM_W2  + i] = W2[i];
    }
    if (t < HID_) sm[SM_B1 + t] = b1[t];
    if (t < C_)  { sm[SM_B2 + t] = b2[t]; sm[SM_WA + t] = Wa[t]; }
    if (t == 0)   sm[SM_BA] = ba[0];
    __syncthreads();

    int r = t >> 4, cpos = t & 15;
    int pbase = tile_base + r*W_ + cpos;

    // x row packed into 32 f32x2 (channels 2p, 2p+1)
    u64 xr2[32];
    {
        float xa[C_];
        #pragma unroll
        for (int c = 0; c < C_; ++c) xa[c] = x[pbase + c*HW_];
        #pragma unroll
        for (int p = 0; p < 32; ++p) xr2[p] = pack2(xa[2*p], xa[2*p+1]);
    }

    // alpha = sigmoid(x . Wa + ba), packed dot
    float alpha;
    {
        const ulonglong2* war = (const ulonglong2*)(sm + SM_WA);
        u64 a0 = 0, a1 = 0;
        #pragma unroll
        for (int q = 0; q < 16; ++q) {
            ulonglong2 w = war[q];
            a0 = ffma2(xr2[2*q],   w.x, a0);
            a1 = ffma2(xr2[2*q+1], w.y, a1);
        }
        float l0,h0,l1,h1;
        unpack2(a0,l0,h0); unpack2(a1,l1,h1);
        alpha = fast_sigmoid(((l0+h0)+(l1+h1)) + sm[SM_BA]);
    }

    // output accumulators: 32 f32x2 (channels 2j, 2j+1), init = b2
    u64 acc2[32];
    #pragma unroll
    for (int j = 0; j < 32; ++j) acc2[j] = pack2(sm[SM_B2 + 2*j], sm[SM_B2 + 2*j+1]);

    #pragma unroll 4
    for (int d = 0; d < HID_; d += 2) {
        const ulonglong2* w1a = (const ulonglong2*)(sm + SM_W1T + d*C_);
        const ulonglong2* w1b = (const ulonglong2*)(sm + SM_W1T + (d+1)*C_);
        u64 a0=0,a1=0,a2=0,a3=0;   // dot d
        u64 c0=0,c1=0,c2=0,c3=0;   // dot d+1
        #pragma unroll
        for (int q = 0; q < 16; q += 2) {
            ulonglong2 wA = w1a[q], wA2 = w1a[q+1];
            ulonglong2 wB = w1b[q], wB2 = w1b[q+1];
            a0 = ffma2(xr2[2*q],   wA.x,  a0);
            a1 = ffma2(xr2[2*q+1], wA.y,  a1);
            a2 = ffma2(xr2[2*q+2], wA2.x, a2);
            a3 = ffma2(xr2[2*q+3], wA2.y, a3);
            c0 = ffma2(xr2[2*q],   wB.x,  c0);
            c1 = ffma2(xr2[2*q+1], wB.y,  c1);
            c2 = ffma2(xr2[2*q+2], wB2.x, c2);
            c3 = ffma2(xr2[2*q+3], wB2.y, c3);
        }
        float sA, sB;
        {
            float l0,h0,l1,h1,l2,h2,l3,h3;
            unpack2(a0,l0,h0); unpack2(a1,l1,h1); unpack2(a2,l2,h2); unpack2(a3,l3,h3);
            sA = (((l0+h0)+(l1+h1)) + ((l2+h2)+(l3+h3))) + sm[SM_B1 + d];
            unpack2(c0,l0,h0); unpack2(c1,l1,h1); unpack2(c2,l2,h2); unpack2(c3,l3,h3);
            sB = (((l0+h0)+(l1+h1)) + ((l2+h2)+(l3+h3))) + sm[SM_B1 + d + 1];
        }
        float hvA = gelu_tanh(sA);
        float hvB = gelu_tanh(sB);
        u64 hA2 = pack2(hvA, hvA);
        u64 hB2 = pack2(hvB, hvB);
        const ulonglong2* w2a = (const ulonglong2*)(sm + SM_W2 + d*C_);
        const ulonglong2* w2b = (const ulonglong2*)(sm + SM_W2 + (d+1)*C_);
        #pragma unroll
        for (int q = 0; q < 16; ++q) {
            ulonglong2 wA = w2a[q];
            ulonglong2 wB = w2b[q];
            acc2[2*q]   = ffma2(hA2, wA.x, acc2[2*q]);
            acc2[2*q+1] = ffma2(hA2, wA.y, acc2[2*q+1]);
            acc2[2*q]   = ffma2(hB2, wB.x, acc2[2*q]);
            acc2[2*q+1] = ffma2(hB2, wB.y, acc2[2*q+1]);
        }
    }

    int aoff = b*HW_ + (gh*T_ + r)*W_ + gw*T_ + cpos;
    alp[aoff] = alpha;
    #pragma unroll
    for (int j = 0; j < 32; ++j) {
        float d0, d1;
        unpack2(acc2[j], d0, d1);
        int c = 2*j;
        int off0 = pbase + c*HW_;
        int off1 = off0 + HW_;
        det[off0]   = d0;
        det[off1]   = d1;
        float x0 = x[off0], x1 = x[off1];   // L2/L1-hot reload, frees xr2 early
        heavy[off0] = fmaf(alpha, d0, x0);
        heavy[off1] = fmaf(alpha, d1, x1);
    }
}

// ---------------- launcher ----------------
extern "C" void kernel_launch(void* const* d_in, const int* in_sizes, int n_in,
                              void* d_out, int out_size) {
    const float* x  = (const float*)d_in[0];
    const float* u  = (const float*)d_in[1];
    const float* W1 = (const float*)d_in[2];
    const float* b1 = (const float*)d_in[3];
    const float* W2 = (const float*)d_in[4];
    const float* b2 = (const float*)d_in[5];
    const float* Wa = (const float*)d_in[6];
    const float* ba = (const float*)d_in[7];
    float* out = (float*)d_out;

    cudaFuncSetAttribute(main_kernel,
                         cudaFuncAttributeMaxDynamicSharedMemorySize, SMEM_BYTES);

    gate_kernel<<<1, 1024>>>(u, out);
    select_kernel<<<32, 256>>>(u);
    main_kernel<<<B_*K_, 256, SMEM_BYTES>>>(x, W1, b1, W2, b2, Wa, ba, out);
}

// round 3
// speedup vs baseline: 1.2027x; 1.1327x over previous
#include <cuda_runtime.h>

// ---------------- problem constants ----------------
#define B_    2
#define C_    64
#define H_    512
#define W_    512
#define T_    16
#define K_    1024          // tiles per sample
#define KMAX_ 256
#define HID_  128
#define HW_   (H_*W_)       // 262144
#define CHW_  (C_*HW_)      // 16777216

// output layout (flatten-concat of the tuple, all f32)
#define HEAVY_OFF  0
#define DET_OFF    33554432
#define ALPHA_OFF  67108864
#define P_OFF      67633152
#define G_OFF      67635200
#define COST_OFF   67637248
#define BL_OFF     67637249

__device__ int   g_sel[B_*K_];
__device__ float g_W1T[HID_*C_];   // [d][c]

typedef unsigned long long u64;

// ---------------- packed f32x2 helpers ----------------
__device__ __forceinline__ u64 pack2(float lo, float hi) {
    u64 r; asm("mov.b64 %0, {%1, %2};" : "=l"(r) : "f"(lo), "f"(hi)); return r;
}
__device__ __forceinline__ void unpack2(u64 v, float& lo, float& hi) {
    asm("mov.b64 {%0, %1}, %2;" : "=f"(lo), "=f"(hi) : "l"(v));
}
__device__ __forceinline__ u64 ffma2(u64 a, u64 b, u64 c) {
    u64 d; asm("fma.rn.f32x2 %0, %1, %2, %3;" : "=l"(d) : "l"(a), "l"(b), "l"(c));
    return d;
}

// ---------------- math helpers ----------------
__device__ __forceinline__ float fast_sigmoid(float v) {
    return __fdividef(1.f, 1.f + __expf(-v));
}
__device__ __forceinline__ float gelu_tanh(float v) {
    float z  = 0.7978845608028654f * fmaf(0.044715f * v, v * v, v);
    float th; asm("tanh.approx.f32 %0, %1;" : "=f"(th) : "f"(z));
    return 0.5f * v * (1.f + th);
}

// ---------------- gate / stats kernel ----------------
__global__ void gate_kernel(const float* __restrict__ u, float* __restrict__ out) {
    __shared__ float red[1024];
    int t = threadIdx.x;
    float partial = 0.f;
    #pragma unroll
    for (int e = t; e < B_*K_; e += 1024) {
        float uv = u[e];
        float p  = fast_sigmoid(uv);
        float hard = (uv >= 0.f) ? 1.f : 0.f;
        float gate = (hard + p) - p;
        out[P_OFF + e] = p;
        out[G_OFF + e] = gate;
        partial += fmaf(p, 0.9f, 0.1f);
    }
    red[t] = partial;
    __syncthreads();
    for (int s = 512; s > 0; s >>= 1) {
        if (t < s) red[t] += red[t + s];
        __syncthreads();
    }
    if (t == 0) {
        float cost = red[0];
        out[COST_OFF] = cost;
        float bl = cost - 1024.f;
        out[BL_OFF] = bl > 0.f ? bl : 0.f;
    }
}

// ---------------- selection kernel (rank-count top-KMAX) ----------------
__global__ void select_kernel(const float* __restrict__ u) {
    __shared__ float us[K_];
    int b   = blockIdx.x >> 4;
    int seg = blockIdx.x & 15;
    int t   = threadIdx.x;
    for (int i = t; i < K_; i += 256) us[i] = u[b*K_ + i];
    __syncthreads();
    int e   = seg*64 + (t >> 2);
    int sub = t & 3;
    float ue = us[e];
    int cnt = 0;
    if (ue >= 0.f) {
        int j0 = sub * 256;
        #pragma unroll 4
        for (int j = j0; j < j0 + 256; ++j) {
            float uj = us[j];
            if (uj >= 0.f && (uj > ue || (uj == ue && j < e))) cnt++;
        }
    }
    cnt += __shfl_xor_sync(0xFFFFFFFFu, cnt, 1);
    cnt += __shfl_xor_sync(0xFFFFFFFFu, cnt, 2);
    if (sub == 0) g_sel[b*K_ + e] = (ue >= 0.f && cnt < KMAX_) ? 1 : 0;
}

// ---------------- W1 transpose kernel (tiny, once per launch) ----------------
__global__ void transpose_kernel(const float* __restrict__ W1) {
    __shared__ float s[C_*HID_];
    int t = threadIdx.x;
    for (int i = t; i < C_*HID_; i += 256) s[i] = W1[i];     // s[c*128+d]
    __syncthreads();
    for (int i = t; i < C_*HID_; i += 256) {
        int d = i >> 6, c = i & 63;
        g_W1T[i] = s[c*HID_ + d];                            // [d][c], coalesced out
    }
}

// ---------------- main kernel ----------------
// grid = 2*B*K blocks, 256 threads. Each block = half a tile (128 px).
// Heavy: lanes 0-15 of each warp handle a pixel's channels 0-31, lanes 16-31
// the same pixel's channels 32-63 (shfl_xor(16) joins GEMM1 partial dots).
// Weight rows padded [32 | 4 | 32] floats so the two half-warp LDS.128
// broadcasts hit disjoint banks.
#define ROWP   72                 // padded row stride in floats
#define SM_W1  0                  // 128*72
#define SM_W2  9216               // 128*72
#define SM_B1  18432              // 128
#define SM_B2  18560              // 68 (padded halves)
#define SM_WA  18628              // 68
#define SM_BA  18696
#define SMEM_FLOATS 18700
#define SMEM_BYTES (SMEM_FLOATS*4)

__global__ void __launch_bounds__(256, 2)
main_kernel(const float* __restrict__ x,
            const float* __restrict__ W2g, const float* __restrict__ b1,
            const float* __restrict__ b2, const float* __restrict__ Wa,
            const float* __restrict__ ba,
            float* __restrict__ out) {
    extern __shared__ float sm[];
    int blk  = blockIdx.x;
    int tile = blk >> 1;
    int half = blk & 1;
    int b    = tile >> 10;
    int k    = tile & (K_-1);
    int gh   = k >> 5, gw = k & 31;
    int t    = threadIdx.x;

    int tile_base = b*CHW_ + (gh*T_)*W_ + gw*T_;
    float* heavy = out + HEAVY_OFF;
    float* det   = out + DET_OFF;
    float* alp   = out + ALPHA_OFF;

    if (!g_sel[tile]) {
        // ---- cheap path: heavy = x, detail = 0, alpha = 0 (128 px) ----
        // 2048 float4s over (c, 32 groups of 4 px); 8 per thread, deep MLP.
        int px0 = half*128;
        #pragma unroll 8
        for (int i = t; i < 2048; i += 256) {
            int c = i >> 5; int l = i & 31;
            int px = px0 + l*4;
            int off = tile_base + c*HW_ + (px >> 4)*W_ + (px & 15);
            float4 v = *(const float4*)(x + off);
            *(float4*)(heavy + off) = v;
            *(float4*)(det   + off) = make_float4(0.f,0.f,0.f,0.f);
        }
        if (t < 32) {
            int px = px0 + t*4;
            int aoff = b*HW_ + (gh*T_ + (px >> 4))*W_ + gw*T_ + (px & 15);
            *(float4*)(alp + aoff) = make_float4(0.f,0.f,0.f,0.f);
        }
        return;
    }

    // ---- stage weights in padded shared layout (coalesced global reads) ----
    for (int i = t; i < HID_*C_; i += 256) {
        int d = i >> 6, c = i & 63;
        int dst = d*ROWP + c + ((c >= 32) ? 4 : 0);
        sm[SM_W1 + dst] = g_W1T[i];
        sm[SM_W2 + dst] = W2g[i];
    }
    if (t < HID_) sm[SM_B1 + t] = b1[t];
    if (t < C_) {
        int dst = t + ((t >= 32) ? 4 : 0);
        sm[SM_B2 + dst] = b2[t];
        sm[SM_WA + dst] = Wa[t];
    }
    if (t == 0) sm[SM_BA] = ba[0];
    __syncthreads();

    int lane  = t & 31;
    int lhalf = lane >> 4;                       // channel half
    int pxl   = (t >> 5)*16 + (lane & 15);       // 0..127
    int px    = half*128 + pxl;
    int r     = px >> 4, cpos = px & 15;
    int pbase = tile_base + r*W_ + cpos;
    int cbase = lhalf*32;
    int woff  = lhalf*36;                        // padded half offset (floats)

    // x: this thread's 32 channels, packed
    u64 xr2[16];
    #pragma unroll
    for (int j = 0; j < 16; ++j) {
        float lo = x[pbase + (cbase + 2*j    )*HW_];
        float hi = x[pbase + (cbase + 2*j + 1)*HW_];
        xr2[j] = pack2(lo, hi);
    }

    // alpha = sigmoid(x . Wa + ba): half-dot + shfl join
    float alpha;
    {
        const ulonglong2* war = (const ulonglong2*)(sm + SM_WA + woff);
        u64 a0 = 0, a1 = 0;
        #pragma unroll
        for (int q = 0; q < 8; ++q) {
            ulonglong2 w = war[q];
            a0 = ffma2(xr2[2*q],   w.x, a0);
            a1 = ffma2(xr2[2*q+1], w.y, a1);
        }
        float l0,h0,l1,h1;
        unpack2(a0,l0,h0); unpack2(a1,l1,h1);
        float part = (l0+h0) + (l1+h1);
        float other = __shfl_xor_sync(0xFFFFFFFFu, part, 16);
        alpha = fast_sigmoid((part + other) + sm[SM_BA]);
    }

    // accumulators: this thread's 32 output channels
    u64 acc2[16];
    #pragma unroll
    for (int j = 0; j < 16; ++j)
        acc2[j] = pack2(sm[SM_B2 + woff + 2*j], sm[SM_B2 + woff + 2*j + 1]);

    const float* smW1 = sm + SM_W1 + woff;
    const float* smW2 = sm + SM_W2 + woff;

    #pragma unroll 2
    for (int d = 0; d < HID_; d += 2) {
        const ulonglong2* wa_ = (const ulonglong2*)(smW1 + d*ROWP);
        const ulonglong2* wb_ = (const ulonglong2*)(smW1 + (d+1)*ROWP);
        u64 s0=0,s1=0,s2=0,s3=0;     // dot d (half)
        u64 r0=0,r1=0,r2=0,r3=0;     // dot d+1 (half)
        #pragma unroll
        for (int q = 0; q < 8; q += 2) {
            ulonglong2 wA = wa_[q], wA2 = wa_[q+1];
            ulonglong2 wB = wb_[q], wB2 = wb_[q+1];
            s0 = ffma2(xr2[2*q],   wA.x,  s0);
            s1 = ffma2(xr2[2*q+1], wA.y,  s1);
            s2 = ffma2(xr2[2*q+2], wA2.x, s2);
            s3 = ffma2(xr2[2*q+3], wA2.y, s3);
            r0 = ffma2(xr2[2*q],   wB.x,  r0);
            r1 = ffma2(xr2[2*q+1], wB.y,  r1);
            r2 = ffma2(xr2[2*q+2], wB2.x, r2);
            r3 = ffma2(xr2[2*q+3], wB2.y, r3);
        }
        float pd0, pd1;
        {
            float l0,h0,l1,h1,l2,h2,l3,h3;
            unpack2(s0,l0,h0); unpack2(s1,l1,h1); unpack2(s2,l2,h2); unpack2(s3,l3,h3);
            pd0 = ((l0+h0)+(l1+h1)) + ((l2+h2)+(l3+h3));
            unpack2(r0,l0,h0); unpack2(r1,l1,h1); unpack2(r2,l2,h2); unpack2(r3,l3,h3);
            pd1 = ((l0+h0)+(l1+h1)) + ((l2+h2)+(l3+h3));
        }
        float od0 = __shfl_xor_sync(0xFFFFFFFFu, pd0, 16);
        float od1 = __shfl_xor_sync(0xFFFFFFFFu, pd1, 16);
        float hv0 = gelu_tanh((pd0 + od0) + sm[SM_B1 + d]);
        float hv1 = gelu_tanh((pd1 + od1) + sm[SM_B1 + d + 1]);
        u64 h02 = pack2(hv0, hv0);
        u64 h12 = pack2(hv1, hv1);
        const ulonglong2* v0 = (const ulonglong2*)(smW2 + d*ROWP);
        const ulonglong2* v1 = (const ulonglong2*)(smW2 + (d+1)*ROWP);
        #pragma unroll
        for (int q = 0; q < 8; ++q) {
            ulonglong2 wA = v0[q];
            ulonglong2 wB = v1[q];
            acc2[2*q]   = ffma2(h02, wA.x, acc2[2*q]);
            acc2[2*q+1] = ffma2(h02, wA.y, acc2[2*q+1]);
            acc2[2*q]   = ffma2(h12, wB.x, acc2[2*q]);
            acc2[2*q+1] = ffma2(h12, wB.y, acc2[2*q+1]);
        }
    }

    if (lhalf == 0) {
        int aoff = b*HW_ + (gh*T_ + r)*W_ + gw*T_ + cpos;
        alp[aoff] = alpha;
    }
    #pragma unroll
    for (int j = 0; j < 16; ++j) {
        float d0, d1, x0, x1;
        unpack2(acc2[j], d0, d1);
        unpack2(xr2[j],  x0, x1);
        int off0 = pbase + (cbase + 2*j)*HW_;
        int off1 = off0 + HW_;
        det[off0]   = d0;
        det[off1]   = d1;
        heavy[off0] = fmaf(alpha, d0, x0);
        heavy[off1] = fmaf(alpha, d1, x1);
    }
}

// ---------------- launcher ----------------
extern "C" void kernel_launch(void* const* d_in, const int* in_sizes, int n_in,
                              void* d_out, int out_size) {
    const float* x  = (const float*)d_in[0];
    const float* u  = (const float*)d_in[1];
    const float* W1 = (const float*)d_in[2];
    const float* b1 = (const float*)d_in[3];
    const float* W2 = (const float*)d_in[4];
    const float* b2 = (const float*)d_in[5];
    const float* Wa = (const float*)d_in[6];
    const float* ba = (const float*)d_in[7];
    float* out = (float*)d_out;

    cudaFuncSetAttribute(main_kernel,
                         cudaFuncAttributeMaxDynamicSharedMemorySize, SMEM_BYTES);

    gate_kernel<<<1, 1024>>>(u, out);
    select_kernel<<<32, 256>>>(u);
    transpose_kernel<<<1, 256>>>(W1);
    main_kernel<<<2*B_*K_, 256, SMEM_BYTES>>>(x, W2, b1, b2, Wa, ba, out);
}

// round 4
// speedup vs baseline: 1.2400x; 1.0310x over previous
#include <cuda_runtime.h>

// ---------------- problem constants ----------------
#define B_    2
#define C_    64
#define H_    512
#define W_    512
#define T_    16
#define K_    1024          // tiles per sample
#define KMAX_ 256
#define HID_  128
#define HW_   (H_*W_)       // 262144
#define CHW_  (C_*HW_)      // 16777216

// output layout (flatten-concat of the tuple, all f32)
#define HEAVY_OFF  0
#define DET_OFF    33554432
#define ALPHA_OFF  67108864
#define P_OFF      67633152
#define G_OFF      67635200
#define COST_OFF   67637248
#define BL_OFF     67637249

__device__ int   g_sel[B_*K_];
__device__ float g_W1T[HID_*C_];   // [d][c]

typedef unsigned long long u64;

// ---------------- packed f32x2 helpers ----------------
__device__ __forceinline__ u64 pack2(float lo, float hi) {
    u64 r; asm("mov.b64 %0, {%1, %2};" : "=l"(r) : "f"(lo), "f"(hi)); return r;
}
__device__ __forceinline__ void unpack2(u64 v, float& lo, float& hi) {
    asm("mov.b64 {%0, %1}, %2;" : "=f"(lo), "=f"(hi) : "l"(v));
}
__device__ __forceinline__ u64 ffma2(u64 a, u64 b, u64 c) {
    u64 d; asm("fma.rn.f32x2 %0, %1, %2, %3;" : "=l"(d) : "l"(a), "l"(b), "l"(c));
    return d;
}

// ---------------- math helpers ----------------
__device__ __forceinline__ float fast_sigmoid(float v) {
    return __fdividef(1.f, 1.f + __expf(-v));
}
__device__ __forceinline__ float gelu_tanh(float v) {
    float z  = 0.7978845608028654f * fmaf(0.044715f * v, v * v, v);
    float th; asm("tanh.approx.f32 %0, %1;" : "=f"(th) : "f"(z));
    return 0.5f * v * (1.f + th);
}

// ---------------- prep kernel: select (blk 0-31) + gate (32) + W1T (33) ----
__global__ void __launch_bounds__(256)
prep_kernel(const float* __restrict__ u, const float* __restrict__ W1,
            float* __restrict__ out) {
    __shared__ float sh[64*129];
    int blk = blockIdx.x;
    int t   = threadIdx.x;

    if (blk < 32) {
        // ---- selection: rank-count top-KMAX ----
        float* us = sh;
        int b   = blk >> 4;
        int seg = blk & 15;
        for (int i = t; i < K_; i += 256) us[i] = u[b*K_ + i];
        __syncthreads();
        int e   = seg*64 + (t >> 2);
        int sub = t & 3;
        float ue = us[e];
        int cnt = 0;
        if (ue >= 0.f) {
            int j0 = sub * 256;
            #pragma unroll 4
            for (int j = j0; j < j0 + 256; ++j) {
                float uj = us[j];
                if (uj >= 0.f && (uj > ue || (uj == ue && j < e))) cnt++;
            }
        }
        cnt += __shfl_xor_sync(0xFFFFFFFFu, cnt, 1);
        cnt += __shfl_xor_sync(0xFFFFFFFFu, cnt, 2);
        if (sub == 0) g_sel[b*K_ + e] = (ue >= 0.f && cnt < KMAX_) ? 1 : 0;
    } else if (blk == 32) {
        // ---- gate probabilities + cost reduction ----
        float partial = 0.f;
        #pragma unroll
        for (int e = t; e < B_*K_; e += 256) {
            float uv = u[e];
            float p  = fast_sigmoid(uv);
            float hard = (uv >= 0.f) ? 1.f : 0.f;
            float gate = (hard + p) - p;
            out[P_OFF + e] = p;
            out[G_OFF + e] = gate;
            partial += fmaf(p, 0.9f, 0.1f);
        }
        #pragma unroll
        for (int s = 16; s > 0; s >>= 1)
            partial += __shfl_xor_sync(0xFFFFFFFFu, partial, s);
        if ((t & 31) == 0) sh[t >> 5] = partial;
        __syncthreads();
        if (t == 0) {
            float cost = 0.f;
            #pragma unroll
            for (int w = 0; w < 8; ++w) cost += sh[w];
            out[COST_OFF] = cost;
            float bl = cost - 1024.f;      // BUDGET_TOTAL*B
            out[BL_OFF] = bl > 0.f ? bl : 0.f;
        }
    } else {
        // ---- W1 transpose (padded smem, conflict-free) ----
        for (int i = t; i < C_*HID_; i += 256) {
            int c = i >> 7, d = i & 127;
            sh[c*129 + d] = W1[i];
        }
        __syncthreads();
        for (int i = t; i < C_*HID_; i += 256) {
            int d = i >> 6, c = i & 63;
            g_W1T[i] = sh[c*129 + d];
        }
    }
}

// ---------------- main kernel ----------------
// grid = B*K blocks (one FULL tile each), 256 threads.
// Heavy: thread = (pixel pair {px, px+128}, channel half). Lanes 0-15 own
// channels 0-31 of their pixels, lanes 16-31 own channels 32-63; GEMM1 dots
// joined via shfl_xor(16). Each weight LDS.128 now feeds 2 pixels (1:4
// LDS:FFMA2 ratio). Weight rows padded [32 | 4 | 32] floats.
#define ROWP   72
#define SM_W1  0                  // 128*72
#define SM_W2  9216               // 128*72
#define SM_B1  18432              // 128
#define SM_B2  18560              // 68
#define SM_WA  18628              // 68
#define SM_BA  18696
#define SMEM_FLOATS 18700
#define SMEM_BYTES (SMEM_FLOATS*4)

__global__ void __launch_bounds__(256)
main_kernel(const float* __restrict__ x,
            const float* __restrict__ W2g, const float* __restrict__ b1,
            const float* __restrict__ b2, const float* __restrict__ Wa,
            const float* __restrict__ ba,
            float* __restrict__ out) {
    extern __shared__ float sm[];
    int tile = blockIdx.x;
    int b    = tile >> 10;
    int k    = tile & (K_-1);
    int gh   = k >> 5, gw = k & 31;
    int t    = threadIdx.x;

    int tile_base = b*CHW_ + (gh*T_)*W_ + gw*T_;
    float* heavy = out + HEAVY_OFF;
    float* det   = out + DET_OFF;
    float* alp   = out + ALPHA_OFF;

    if (!g_sel[tile]) {
        // ---- cheap path: heavy = x, detail = 0, alpha = 0 (full tile) ----
        #pragma unroll 8
        for (int i = t; i < 4096; i += 256) {
            int c = i >> 6; int l = i & 63;           // 64 float4 per plane
            int off = tile_base + c*HW_ + (l >> 2)*W_ + (l & 3)*4;
            float4 v = *(const float4*)(x + off);
            *(float4*)(heavy + off) = v;
            *(float4*)(det   + off) = make_float4(0.f,0.f,0.f,0.f);
        }
        if (t < 64) {
            int aoff = b*HW_ + (gh*T_ + (t >> 2))*W_ + gw*T_ + (t & 3)*4;
            *(float4*)(alp + aoff) = make_float4(0.f,0.f,0.f,0.f);
        }
        return;
    }

    // ---- stage weights in padded shared layout ----
    for (int i = t; i < HID_*C_; i += 256) {
        int d = i >> 6, c = i & 63;
        int dst = d*ROWP + c + ((c >= 32) ? 4 : 0);
        sm[SM_W1 + dst] = g_W1T[i];
        sm[SM_W2 + dst] = W2g[i];
    }
    if (t < HID_) sm[SM_B1 + t] = b1[t];
    if (t < C_) {
        int dst = t + ((t >= 32) ? 4 : 0);
        sm[SM_B2 + dst] = b2[t];
        sm[SM_WA + dst] = Wa[t];
    }
    if (t == 0) sm[SM_BA] = ba[0];
    __syncthreads();

    int lane  = t & 31;
    int lh    = lane >> 4;                        // channel half
    int pxa   = (t >> 5)*16 + (lane & 15);        // 0..127 ; pxb = pxa+128
    int ra    = pxa >> 4, cpos = pxa & 15;
    int pbaseA = tile_base + ra*W_ + cpos;
    int pbaseB = pbaseA + 8*W_;                   // +128 px = +8 rows
    int cbase  = lh*32;
    int woff   = lh*36;

    // x for both pixels, this thread's 32 channels, packed
    u64 xa2[16], xb2[16];
    #pragma unroll
    for (int j = 0; j < 16; ++j) {
        int o = (cbase + 2*j)*HW_;
        xa2[j] = pack2(x[pbaseA + o], x[pbaseA + o + HW_]);
        xb2[j] = pack2(x[pbaseB + o], x[pbaseB + o + HW_]);
    }

    // alpha for both pixels
    float alphaA, alphaB;
    {
        const ulonglong2* war = (const ulonglong2*)(sm + SM_WA + woff);
        u64 a0=0, a1=0, c0=0, c1=0;
        #pragma unroll
        for (int q = 0; q < 8; ++q) {
            ulonglong2 w = war[q];
            a0 = ffma2(xa2[2*q],   w.x, a0);
            a1 = ffma2(xa2[2*q+1], w.y, a1);
            c0 = ffma2(xb2[2*q],   w.x, c0);
            c1 = ffma2(xb2[2*q+1], w.y, c1);
        }
        float l0,h0,l1,h1;
        unpack2(a0,l0,h0); unpack2(a1,l1,h1);
        float pa = (l0+h0)+(l1+h1);
        unpack2(c0,l0,h0); unpack2(c1,l1,h1);
        float pb = (l0+h0)+(l1+h1);
        float oa = __shfl_xor_sync(0xFFFFFFFFu, pa, 16);
        float ob = __shfl_xor_sync(0xFFFFFFFFu, pb, 16);
        alphaA = fast_sigmoid((pa + oa) + sm[SM_BA]);
        alphaB = fast_sigmoid((pb + ob) + sm[SM_BA]);
    }

    // accumulators (32 out-channels per pixel)
    u64 acca[16], accb[16];
    #pragma unroll
    for (int j = 0; j < 16; ++j) {
        u64 bb = pack2(sm[SM_B2 + woff + 2*j], sm[SM_B2 + woff + 2*j + 1]);
        acca[j] = bb; accb[j] = bb;
    }

    const float* smW1 = sm + SM_W1 + woff;
    const float* smW2 = sm + SM_W2 + woff;

    #pragma unroll 2
    for (int d = 0; d < HID_; d += 2) {
        const ulonglong2* w0 = (const ulonglong2*)(smW1 + d*ROWP);
        const ulonglong2* w1 = (const ulonglong2*)(smW1 + (d+1)*ROWP);
        u64 sa0=0,sa1=0, sb0=0,sb1=0;   // row d, px a / b
        u64 ta0=0,ta1=0, tb0=0,tb1=0;   // row d+1
        #pragma unroll
        for (int q = 0; q < 8; ++q) {
            ulonglong2 wv0 = w0[q];
            ulonglong2 wv1 = w1[q];
            sa0 = ffma2(xa2[2*q],   wv0.x, sa0);
            sa1 = ffma2(xa2[2*q+1], wv0.y, sa1);
            sb0 = ffma2(xb2[2*q],   wv0.x, sb0);
            sb1 = ffma2(xb2[2*q+1], wv0.y, sb1);
            ta0 = ffma2(xa2[2*q],   wv1.x, ta0);
            ta1 = ffma2(xa2[2*q+1], wv1.y, ta1);
            tb0 = ffma2(xb2[2*q],   wv1.x, tb0);
            tb1 = ffma2(xb2[2*q+1], wv1.y, tb1);
        }
        float pA0, pA1, pB0, pB1;
        {
            float l0,h0,l1,h1;
            unpack2(sa0,l0,h0); unpack2(sa1,l1,h1); pA0 = (l0+h0)+(l1+h1);
            unpack2(ta0,l0,h0); unpack2(ta1,l1,h1); pA1 = (l0+h0)+(l1+h1);
            unpack2(sb0,l0,h0); unpack2(sb1,l1,h1); pB0 = (l0+h0)+(l1+h1);
            unpack2(tb0,l0,h0); unpack2(tb1,l1,h1); pB1 = (l0+h0)+(l1+h1);
        }
        float qA0 = __shfl_xor_sync(0xFFFFFFFFu, pA0, 16);
        float qA1 = __shfl_xor_sync(0xFFFFFFFFu, pA1, 16);
        float qB0 = __shfl_xor_sync(0xFFFFFFFFu, pB0, 16);
        float qB1 = __shfl_xor_sync(0xFFFFFFFFu, pB1, 16);
        float bi0 = sm[SM_B1 + d], bi1 = sm[SM_B1 + d + 1];
        float hA0 = gelu_tanh((pA0 + qA0) + bi0);
        float hA1 = gelu_tanh((pA1 + qA1) + bi1);
        float hB0 = gelu_tanh((pB0 + qB0) + bi0);
        float hB1 = gelu_tanh((pB1 + qB1) + bi1);
        u64 hA02 = pack2(hA0, hA0), hA12 = pack2(hA1, hA1);
        u64 hB02 = pack2(hB0, hB0), hB12 = pack2(hB1, hB1);
        const ulonglong2* v0 = (const ulonglong2*)(smW2 + d*ROWP);
        const ulonglong2* v1 = (const ulonglong2*)(smW2 + (d+1)*ROWP);
        #pragma unroll
        for (int q = 0; q < 8; ++q) {
            ulonglong2 wv0 = v0[q];
            ulonglong2 wv1 = v1[q];
            acca[2*q]   = ffma2(hA02, wv0.x, acca[2*q]);
            acca[2*q+1] = ffma2(hA02, wv0.y, acca[2*q+1]);
            acca[2*q]   = ffma2(hA12, wv1.x, acca[2*q]);
            acca[2*q+1] = ffma2(hA12, wv1.y, acca[2*q+1]);
            accb[2*q]   = ffma2(hB02, wv0.x, accb[2*q]);
            accb[2*q+1] = ffma2(hB02, wv0.y, accb[2*q+1]);
            accb[2*q]   = ffma2(hB12, wv1.x, accb[2*q]);
            accb[2*q+1] = ffma2(hB12, wv1.y, accb[2*q+1]);
        }
    }

    if (lh == 0) {
        int arow = b*HW_ + (gh*T_ + ra)*W_ + gw*T_ + cpos;
        alp[arow] = alphaA;
        alp[arow + 8*W_] = alphaB;
    }
    #pragma unroll
    for (int j = 0; j < 16; ++j) {
        int o = (cbase + 2*j)*HW_;
        float d0, d1, x0, x1;
        unpack2(acca[j], d0, d1);
        unpack2(xa2[j],  x0, x1);
        det[pbaseA + o]        = d0;
        det[pbaseA + o + HW_]  = d1;
        heavy[pbaseA + o]       = fmaf(alphaA, d0, x0);
        heavy[pbaseA + o + HW_] = fmaf(alphaA, d1, x1);
        unpack2(accb[j], d0, d1);
        unpack2(xb2[j],  x0, x1);
        det[pbaseB + o]        = d0;
        det[pbaseB + o + HW_]  = d1;
        heavy[pbaseB + o]       = fmaf(alphaB, d0, x0);
        heavy[pbaseB + o + HW_] = fmaf(alphaB, d1, x1);
    }
}

// ---------------- launcher ----------------
extern "C" void kernel_launch(void* const* d_in, const int* in_sizes, int n_in,
                              void* d_out, int out_size) {
    const float* x  = (const float*)d_in[0];
    const float* u  = (const float*)d_in[1];
    const float* W1 = (const float*)d_in[2];
    const float* b1 = (const float*)d_in[3];
    const float* W2 = (const float*)d_in[4];
    const float* b2 = (const float*)d_in[5];
    const float* Wa = (const float*)d_in[6];
    const float* ba = (const float*)d_in[7];
    float* out = (float*)d_out;

    cudaFuncSetAttribute(main_kernel,
                         cudaFuncAttributeMaxDynamicSharedMemorySize, SMEM_BYTES);

    prep_kernel<<<34, 256>>>(u, W1, out);
    main_kernel<<<B_*K_, 256, SMEM_BYTES>>>(x, W2, b1, b2, Wa, ba, out);
}

// round 5
// speedup vs baseline: 1.2744x; 1.0277x over previous
#include <cuda_runtime.h>

// ---------------- problem constants ----------------
#define B_    2
#define C_    64
#define H_    512
#define W_    512
#define T_    16
#define K_    1024          // tiles per sample
#define KMAX_ 256
#define HID_  128
#define HW_   (H_*W_)       // 262144
#define CHW_  (C_*HW_)      // 16777216

// output layout (flatten-concat of the tuple, all f32)
#define HEAVY_OFF  0
#define DET_OFF    33554432
#define ALPHA_OFF  67108864
#define P_OFF      67633152
#define G_OFF      67635200
#define COST_OFF   67637248
#define BL_OFF     67637249

__device__ int   g_sel[B_*K_];
__device__ float g_W1T[HID_*C_];   // [d][c]

typedef unsigned long long u64;

// ---------------- packed f32x2 helpers ----------------
__device__ __forceinline__ u64 pack2(float lo, float hi) {
    u64 r; asm("mov.b64 %0, {%1, %2};" : "=l"(r) : "f"(lo), "f"(hi)); return r;
}
__device__ __forceinline__ void unpack2(u64 v, float& lo, float& hi) {
    asm("mov.b64 {%0, %1}, %2;" : "=f"(lo), "=f"(hi) : "l"(v));
}
__device__ __forceinline__ u64 ffma2(u64 a, u64 b, u64 c) {
    u64 d; asm("fma.rn.f32x2 %0, %1, %2, %3;" : "=l"(d) : "l"(a), "l"(b), "l"(c));
    return d;
}
__device__ __forceinline__ u64 add2(u64 a, u64 b) {
    u64 d; asm("add.rn.f32x2 %0, %1, %2;" : "=l"(d) : "l"(a), "l"(b));
    return d;
}
__device__ __forceinline__ float hsum2(u64 v) {
    float lo, hi; unpack2(v, lo, hi); return lo + hi;
}

// ---------------- math helpers ----------------
__device__ __forceinline__ float fast_sigmoid(float v) {
    return __fdividef(1.f, 1.f + __expf(-v));
}
__device__ __forceinline__ float gelu_tanh(float v) {
    float z  = 0.7978845608028654f * fmaf(0.044715f * v, v * v, v);
    float th; asm("tanh.approx.f32 %0, %1;" : "=f"(th) : "f"(z));
    return 0.5f * v * (1.f + th);
}

// ---------------- prep kernel: select (blk 0-31) + gate (32) + W1T (33) ----
__global__ void __launch_bounds__(256)
prep_kernel(const float* __restrict__ u, const float* __restrict__ W1,
            float* __restrict__ out) {
    __shared__ float sh[64*129];
    int blk = blockIdx.x;
    int t   = threadIdx.x;

    if (blk < 32) {
        float* us = sh;
        int b   = blk >> 4;
        int seg = blk & 15;
        for (int i = t; i < K_; i += 256) us[i] = u[b*K_ + i];
        __syncthreads();
        int e   = seg*64 + (t >> 2);
        int sub = t & 3;
        float ue = us[e];
        int cnt = 0;
        if (ue >= 0.f) {
            int j0 = sub * 256;
            #pragma unroll 4
            for (int j = j0; j < j0 + 256; ++j) {
                float uj = us[j];
                if (uj >= 0.f && (uj > ue || (uj == ue && j < e))) cnt++;
            }
        }
        cnt += __shfl_xor_sync(0xFFFFFFFFu, cnt, 1);
        cnt += __shfl_xor_sync(0xFFFFFFFFu, cnt, 2);
        if (sub == 0) g_sel[b*K_ + e] = (ue >= 0.f && cnt < KMAX_) ? 1 : 0;
    } else if (blk == 32) {
        float partial = 0.f;
        #pragma unroll
        for (int e = t; e < B_*K_; e += 256) {
            float uv = u[e];
            float p  = fast_sigmoid(uv);
            float hard = (uv >= 0.f) ? 1.f : 0.f;
            float gate = (hard + p) - p;
            out[P_OFF + e] = p;
            out[G_OFF + e] = gate;
            partial += fmaf(p, 0.9f, 0.1f);
        }
        #pragma unroll
        for (int s = 16; s > 0; s >>= 1)
            partial += __shfl_xor_sync(0xFFFFFFFFu, partial, s);
        if ((t & 31) == 0) sh[t >> 5] = partial;
        __syncthreads();
        if (t == 0) {
            float cost = 0.f;
            #pragma unroll
            for (int w = 0; w < 8; ++w) cost += sh[w];
            out[COST_OFF] = cost;
            float bl = cost - 1024.f;
            out[BL_OFF] = bl > 0.f ? bl : 0.f;
        }
    } else {
        for (int i = t; i < C_*HID_; i += 256) {
            int c = i >> 7, d = i & 127;
            sh[c*129 + d] = W1[i];
        }
        __syncthreads();
        for (int i = t; i < C_*HID_; i += 256) {
            int d = i >> 6, c = i & 63;
            g_W1T[i] = sh[c*129 + d];
        }
    }
}

// ---------------- main kernel ----------------
// grid = 2*B*K blocks (half-tile each), 256 threads, 2 blocks/SM.
// Heavy: lane quartet per pixel pair. lane = (q<<3)|p : quarter q owns
// channels [16q,16q+16), p indexes 8 pixel-pairs per warp. Thread handles
// pixels pxa = half*64 + w*8 + p and pxb = pxa+128. GEMM1 dots joined by
// shfl_xor(8) + shfl_xor(16) butterfly. Weight rows stored as 4 chunks of
// 16 floats at 20-float stride (16B aligned, conflict-free across quarters).
#define ROWP   80                  // padded row stride (floats)
#define CHK    20                  // per-quarter chunk stride
#define SM_W1  0                   // 128*80
#define SM_W2  10240               // 128*80
#define SM_B1  20480               // 128
#define SM_B2  20608               // 80
#define SM_WA  20688               // 80
#define SM_BA  20768
#define SMEM_FLOATS 20772
#define SMEM_BYTES (SMEM_FLOATS*4)

__global__ void __launch_bounds__(256, 2)
main_kernel(const float* __restrict__ x,
            const float* __restrict__ W2g, const float* __restrict__ b1,
            const float* __restrict__ b2, const float* __restrict__ Wa,
            const float* __restrict__ ba,
            float* __restrict__ out) {
    extern __shared__ float sm[];
    int blk  = blockIdx.x;
    int tile = blk >> 1;
    int half = blk & 1;
    int b    = tile >> 10;
    int k    = tile & (K_-1);
    int gh   = k >> 5, gw = k & 31;
    int t    = threadIdx.x;

    int tile_base = b*CHW_ + (gh*T_)*W_ + gw*T_;
    float* heavy = out + HEAVY_OFF;
    float* det   = out + DET_OFF;
    float* alp   = out + ALPHA_OFF;

    if (!g_sel[tile]) {
        // ---- cheap path: 128 px (rows [half*8, half*8+8)) ----
        int rbase = half*8;
        #pragma unroll 8
        for (int i = t; i < 2048; i += 256) {
            int c = i >> 5; int l = i & 31;
            int off = tile_base + c*HW_ + (rbase + (l >> 2))*W_ + (l & 3)*4;
            float4 v = *(const float4*)(x + off);
            *(float4*)(heavy + off) = v;
            *(float4*)(det   + off) = make_float4(0.f,0.f,0.f,0.f);
        }
        if (t < 32) {
            int aoff = b*HW_ + (gh*T_ + rbase + (t >> 2))*W_ + gw*T_ + (t & 3)*4;
            *(float4*)(alp + aoff) = make_float4(0.f,0.f,0.f,0.f);
        }
        return;
    }

    // ---- stage weights: 4 chunks of 16 floats per row, stride 20 ----
    for (int i = t; i < HID_*C_; i += 256) {
        int d = i >> 6, c = i & 63;
        int dst = d*ROWP + (c >> 4)*CHK + (c & 15);
        sm[SM_W1 + dst] = g_W1T[i];
        sm[SM_W2 + dst] = W2g[i];
    }
    if (t < HID_) sm[SM_B1 + t] = b1[t];
    if (t < C_) {
        int dst = (t >> 4)*CHK + (t & 15);
        sm[SM_B2 + dst] = b2[t];
        sm[SM_WA + dst] = Wa[t];
    }
    if (t == 0) sm[SM_BA] = ba[0];
    __syncthreads();

    int lane = t & 31;
    int q    = lane >> 3;                 // channel quarter 0..3
    int p    = lane & 7;                  // pixel-pair slot in warp
    int w    = t >> 5;
    int pxa  = half*64 + w*8 + p;         // 0..127 ; pxb = pxa+128
    int ra   = pxa >> 4, cpos = pxa & 15;
    int pbaseA = tile_base + ra*W_ + cpos;
    int pbaseB = pbaseA + 8*W_;
    int cbase  = q*16;
    int woff   = q*CHK;

    // x for both pixels, this thread's 16 channels, packed into 8 f32x2
    u64 xa2[8], xb2[8];
    #pragma unroll
    for (int j = 0; j < 8; ++j) {
        int o = (cbase + 2*j)*HW_;
        xa2[j] = pack2(x[pbaseA + o], x[pbaseA + o + HW_]);
        xb2[j] = pack2(x[pbaseB + o], x[pbaseB + o + HW_]);
    }

    // alpha for both pixels (quarter-dot + butterfly)
    float alphaA, alphaB;
    {
        const ulonglong2* war = (const ulonglong2*)(sm + SM_WA + woff);
        ulonglong2 w0 = war[0], w1 = war[1], w2v = war[2], w3 = war[3];
        u64 a0=0, a1=0, c0=0, c1=0;
        a0 = ffma2(xa2[0], w0.x, a0); a1 = ffma2(xa2[1], w0.y, a1);
        a0 = ffma2(xa2[2], w1.x, a0); a1 = ffma2(xa2[3], w1.y, a1);
        a0 = ffma2(xa2[4], w2v.x, a0); a1 = ffma2(xa2[5], w2v.y, a1);
        a0 = ffma2(xa2[6], w3.x, a0); a1 = ffma2(xa2[7], w3.y, a1);
        c0 = ffma2(xb2[0], w0.x, c0); c1 = ffma2(xb2[1], w0.y, c1);
        c0 = ffma2(xb2[2], w1.x, c0); c1 = ffma2(xb2[3], w1.y, c1);
        c0 = ffma2(xb2[4], w2v.x, c0); c1 = ffma2(xb2[5], w2v.y, c1);
        c0 = ffma2(xb2[6], w3.x, c0); c1 = ffma2(xb2[7], w3.y, c1);
        float pa = hsum2(add2(a0, a1));
        float pb = hsum2(add2(c0, c1));
        pa += __shfl_xor_sync(0xFFFFFFFFu, pa, 8);
        pa += __shfl_xor_sync(0xFFFFFFFFu, pa, 16);
        pb += __shfl_xor_sync(0xFFFFFFFFu, pb, 8);
        pb += __shfl_xor_sync(0xFFFFFFFFu, pb, 16);
        alphaA = fast_sigmoid(pa + sm[SM_BA]);
        alphaB = fast_sigmoid(pb + sm[SM_BA]);
    }

    // accumulators: 16 out-channels per pixel
    u64 acca[8], accb[8];
    #pragma unroll
    for (int j = 0; j < 8; ++j) {
        u64 bb = pack2(sm[SM_B2 + woff + 2*j], sm[SM_B2 + woff + 2*j + 1]);
        acca[j] = bb; accb[j] = bb;
    }

    const float* smW1 = sm + SM_W1 + woff;
    const float* smW2 = sm + SM_W2 + woff;

    for (int d = 0; d < HID_; d += 2) {
        const ulonglong2* w1r0 = (const ulonglong2*)(smW1 + d*ROWP);
        const ulonglong2* w1r1 = (const ulonglong2*)(smW1 + d*ROWP + ROWP);
        ulonglong2 p0 = w1r0[0], p1 = w1r0[1], p2 = w1r0[2], p3 = w1r0[3];
        ulonglong2 q0 = w1r1[0], q1 = w1r1[1], q2 = w1r1[2], q3 = w1r1[3];
        // 4 quarter-dots: rows {d,d+1} x px {a,b}
        u64 da0=0,da1=0, db0=0,db1=0, ea0=0,ea1=0, eb0=0,eb1=0;
        da0=ffma2(xa2[0],p0.x,da0); da1=ffma2(xa2[1],p0.y,da1);
        da0=ffma2(xa2[2],p1.x,da0); da1=ffma2(xa2[3],p1.y,da1);
        da0=ffma2(xa2[4],p2.x,da0); da1=ffma2(xa2[5],p2.y,da1);
        da0=ffma2(xa2[6],p3.x,da0); da1=ffma2(xa2[7],p3.y,da1);
        db0=ffma2(xb2[0],p0.x,db0); db1=ffma2(xb2[1],p0.y,db1);
        db0=ffma2(xb2[2],p1.x,db0); db1=ffma2(xb2[3],p1.y,db1);
        db0=ffma2(xb2[4],p2.x,db0); db1=ffma2(xb2[5],p2.y,db1);
        db0=ffma2(xb2[6],p3.x,db0); db1=ffma2(xb2[7],p3.y,db1);
        ea0=ffma2(xa2[0],q0.x,ea0); ea1=ffma2(xa2[1],q0.y,ea1);
        ea0=ffma2(xa2[2],q1.x,ea0); ea1=ffma2(xa2[3],q1.y,ea1);
        ea0=ffma2(xa2[4],q2.x,ea0); ea1=ffma2(xa2[5],q2.y,ea1);
        ea0=ffma2(xa2[6],q3.x,ea0); ea1=ffma2(xa2[7],q3.y,ea1);
        eb0=ffma2(xb2[0],q0.x,eb0); eb1=ffma2(xb2[1],q0.y,eb1);
        eb0=ffma2(xb2[2],q1.x,eb0); eb1=ffma2(xb2[3],q1.y,eb1);
        eb0=ffma2(xb2[4],q2.x,eb0); eb1=ffma2(xb2[5],q2.y,eb1);
        eb0=ffma2(xb2[6],q3.x,eb0); eb1=ffma2(xb2[7],q3.y,eb1);
        float rA0 = hsum2(add2(da0, da1));
        float rB0 = hsum2(add2(db0, db1));
        float rA1 = hsum2(add2(ea0, ea1));
        float rB1 = hsum2(add2(eb0, eb1));
        rA0 += __shfl_xor_sync(0xFFFFFFFFu, rA0, 8);
        rA0 += __shfl_xor_sync(0xFFFFFFFFu, rA0, 16);
        rB0 += __shfl_xor_sync(0xFFFFFFFFu, rB0, 8);
        rB0 += __shfl_xor_sync(0xFFFFFFFFu, rB0, 16);
        rA1 += __shfl_xor_sync(0xFFFFFFFFu, rA1, 8);
        rA1 += __shfl_xor_sync(0xFFFFFFFFu, rA1, 16);
        rB1 += __shfl_xor_sync(0xFFFFFFFFu, rB1, 8);
        rB1 += __shfl_xor_sync(0xFFFFFFFFu, rB1, 16);
        float bi0 = sm[SM_B1 + d], bi1 = sm[SM_B1 + d + 1];
        float hA0 = gelu_tanh(rA0 + bi0);
        float hB0 = gelu_tanh(rB0 + bi0);
        float hA1 = gelu_tanh(rA1 + bi1);
        float hB1 = gelu_tanh(rB1 + bi1);
        u64 hA02 = pack2(hA0, hA0), hA12 = pack2(hA1, hA1);
        u64 hB02 = pack2(hB0, hB0), hB12 = pack2(hB1, hB1);
        const ulonglong2* w2r0 = (const ulonglong2*)(smW2 + d*ROWP);
        const ulonglong2* w2r1 = (const ulonglong2*)(smW2 + d*ROWP + ROWP);
        ulonglong2 r0 = w2r0[0], r1 = w2r0[1], r2 = w2r0[2], r3 = w2r0[3];
        ulonglong2 s0 = w2r1[0], s1 = w2r1[1], s2 = w2r1[2], s3 = w2r1[3];
        acca[0] = ffma2(hA02, r0.x, acca[0]); acca[1] = ffma2(hA02, r0.y, acca[1]);
        acca[2] = ffma2(hA02, r1.x, acca[2]); acca[3] = ffma2(hA02, r1.y, acca[3]);
        acca[4] = ffma2(hA02, r2.x, acca[4]); acca[5] = ffma2(hA02, r2.y, acca[5]);
        acca[6] = ffma2(hA02, r3.x, acca[6]); acca[7] = ffma2(hA02, r3.y, acca[7]);
        acca[0] = ffma2(hA12, s0.x, acca[0]); acca[1] = ffma2(hA12, s0.y, acca[1]);
        acca[2] = ffma2(hA12, s1.x, acca[2]); acca[3] = ffma2(hA12, s1.y, acca[3]);
        acca[4] = ffma2(hA12, s2.x, acca[4]); acca[5] = ffma2(hA12, s2.y, acca[5]);
        acca[6] = ffma2(hA12, s3.x, acca[6]); acca[7] = ffma2(hA12, s3.y, acca[7]);
        accb[0] = ffma2(hB02, r0.x, accb[0]); accb[1] = ffma2(hB02, r0.y, accb[1]);
        accb[2] = ffma2(hB02, r1.x, accb[2]); accb[3] = ffma2(hB02, r1.y, accb[3]);
        accb[4] = ffma2(hB02, r2.x, accb[4]); accb[5] = ffma2(hB02, r2.y, accb[5]);
        accb[6] = ffma2(hB02, r3.x, accb[6]); accb[7] = ffma2(hB02, r3.y, accb[7]);
        accb[0] = ffma2(hB12, s0.x, accb[0]); accb[1] = ffma2(hB12, s0.y, accb[1]);
        accb[2] = ffma2(hB12, s1.x, accb[2]); accb[3] = ffma2(hB12, s1.y, accb[3]);
        accb[4] = ffma2(hB12, s2.x, accb[4]); accb[5] = ffma2(hB12, s2.y, accb[5]);
        accb[6] = ffma2(hB12, s3.x, accb[6]); accb[7] = ffma2(hB12, s3.y, accb[7]);
    }

    if (q == 0) {
        int arow = b*HW_ + (gh*T_ + ra)*W_ + gw*T_ + cpos;
        alp[arow] = alphaA;
        alp[arow + 8*W_] = alphaB;
    }
    #pragma unroll
    for (int j = 0; j < 8; ++j) {
        int o = (cbase + 2*j)*HW_;
        float d0, d1, x0, x1;
        unpack2(acca[j], d0, d1);
        unpack2(xa2[j],  x0, x1);
        det[pbaseA + o]        = d0;
        det[pbaseA + o + HW_]  = d1;
        heavy[pbaseA + o]       = fmaf(alphaA, d0, x0);
        heavy[pbaseA + o + HW_] = fmaf(alphaA, d1, x1);
        unpack2(accb[j], d0, d1);
        unpack2(xb2[j],  x0, x1);
        det[pbaseB + o]        = d0;
        det[pbaseB + o + HW_]  = d1;
        heavy[pbaseB + o]       = fmaf(alphaB, d0, x0);
        heavy[pbaseB + o + HW_] = fmaf(alphaB, d1, x1);
    }
}

// ---------------- launcher ----------------
extern "C" void kernel_launch(void* const* d_in, const int* in_sizes, int n_in,
                              void* d_out, int out_size) {
    const float* x  = (const float*)d_in[0];
    const float* u  = (const float*)d_in[1];
    const float* W1 = (const float*)d_in[2];
    const float* b1 = (const float*)d_in[3];
    const float* W2 = (const float*)d_in[4];
    const float* b2 = (const float*)d_in[5];
    const float* Wa = (const float*)d_in[6];
    const float* ba = (const float*)d_in[7];
    float* out = (float*)d_out;

    cudaFuncSetAttribute(main_kernel,
                         cudaFuncAttributeMaxDynamicSharedMemorySize, SMEM_BYTES);

    prep_kernel<<<34, 256>>>(u, W1, out);
    main_kernel<<<2*B_*K_, 256, SMEM_BYTES>>>(x, W2, b1, b2, Wa, ba, out);
}